// round 1
// baseline (speedup 1.0000x reference)
#include <cuda_runtime.h>
#include <cstdint>

// Problem constants (fixed by setup_inputs)
#define B      2
#define NPTS   8192
#define D      256
#define NBINS  32
#define BIN    256
#define TOPK   16
#define NPROJ  16          // n_bins / 2
#define NCHUNK (B * NBINS) // 64 total chunks across batches

// ---------------- scratch (device globals; no allocation allowed) ------------
__device__ int   g_bin_idx[B * NPTS];
__device__ int   g_order  [B * NPTS];
__device__ float g_pts    [B * NPTS * D];       // 16 MB gathered points
__device__ float g_dm     [NCHUNK * BIN * BIN]; // 16 MB sigmoid(similarity)

// ---------------- K0: zero the 512MB output ----------------------------------
__global__ void k_zero(float4* __restrict__ out, long n4) {
    long i = (long)blockIdx.x * blockDim.x + threadIdx.x;
    long stride = (long)gridDim.x * blockDim.x;
    float4 z = make_float4(0.f, 0.f, 0.f, 0.f);
    for (; i < n4; i += stride) out[i] = z;
}

// ---------------- K1: projection + argmax over [proj, -proj] ------------------
// grid: 256 blocks x 256 threads; block handles 64 points (warp handles 8)
__global__ __launch_bounds__(256) void k_proj_argmax(
    const float* __restrict__ x, const float* __restrict__ cb) {
    __shared__ float cbs[NPROJ][D]; // transposed codebook, first 16 columns
    int tid = threadIdx.x;
    // coalesced read of full codebook (256x32), keep first 16 cols transposed
    for (int e = tid; e < D * 32; e += 256) {
        int d = e >> 5, j = e & 31;
        float v = cb[e];
        if (j < NPROJ) cbs[j][d] = v;
    }
    __syncthreads();

    int warp = tid >> 5, lane = tid & 31;
    for (int i = 0; i < 8; i++) {
        int p = blockIdx.x * 64 + warp * 8 + i; // point in [0, B*NPTS)
        const float* xr = x + (size_t)p * D;
        float acc[NPROJ];
#pragma unroll
        for (int j = 0; j < NPROJ; j++) acc[j] = 0.f;
#pragma unroll
        for (int k = 0; k < 8; k++) {
            int d = lane + 32 * k;
            float xv = xr[d];
#pragma unroll
            for (int j = 0; j < NPROJ; j++) acc[j] += xv * cbs[j][d];
        }
#pragma unroll
        for (int j = 0; j < NPROJ; j++)
#pragma unroll
            for (int off = 16; off; off >>= 1)
                acc[j] += __shfl_xor_sync(0xFFFFFFFFu, acc[j], off);
        if (lane == 0) {
            float best = acc[0]; int bi = 0;
            for (int jj = 1; jj < 2 * NPROJ; jj++) {
                float v = (jj < NPROJ) ? acc[jj] : -acc[jj - NPROJ];
                if (v > best) { best = v; bi = jj; } // first-max wins (argmax semantics)
            }
            g_bin_idx[p] = bi;
        }
    }
}

// ---------------- K2: stable counting sort (argsort by bin id) ---------------
// grid: B blocks x 1024 threads; warp w owns bin w
__global__ __launch_bounds__(1024) void k_stable_sort() {
    int batch = blockIdx.x;
    const int* bi = g_bin_idx + batch * NPTS;
    int* ord = g_order + batch * NPTS;
    __shared__ int off[NBINS + 1];
    int w = threadIdx.x >> 5, lane = threadIdx.x & 31;

    int total = 0;
    for (int it = 0; it < NPTS / 32; it++) {
        int i = it * 32 + lane;
        unsigned m = __ballot_sync(0xFFFFFFFFu, bi[i] == w);
        total += __popc(m);
    }
    if (lane == 0) off[w + 1] = total;
    __syncthreads();
    if (threadIdx.x == 0) {
        off[0] = 0;
        for (int j = 1; j <= NBINS; j++) off[j] += off[j - 1];
    }
    __syncthreads();

    int pos = off[w];
    for (int it = 0; it < NPTS / 32; it++) {
        int i = it * 32 + lane;
        int b = bi[i];
        unsigned m = __ballot_sync(0xFFFFFFFFu, b == w);
        if (b == w) ord[pos + __popc(m & ((1u << lane) - 1u))] = i;
        pos += __popc(m);
    }
}

// ---------------- K3: gather points into sorted order ------------------------
__global__ __launch_bounds__(256) void k_gather(const float* __restrict__ x) {
    long i = (long)blockIdx.x * blockDim.x + threadIdx.x; // over B*NPTS*(D/4)
    const long total = (long)B * NPTS * (D / 4);
    if (i >= total) return;
    int dv = (int)(i & (D / 4 - 1));
    long j = i >> 6;                 // D/4 = 64
    int b = (int)(j >> 13);          // NPTS = 8192
    int src = g_order[j];
    ((float4*)g_pts)[j * (D / 4) + dv] =
        ((const float4*)x)[((long)b * NPTS + src) * (D / 4) + dv];
}

// ---------------- K4: per-chunk GEMM (C = P P^T) + sigmoid -------------------
// grid: NCHUNK*16 blocks; each block computes a 64x64 tile, 256 threads, 4x4 acc
__global__ __launch_bounds__(256) void k_gemm_sigmoid() {
    int bx = blockIdx.x;
    int chunk = bx >> 4;
    int t = bx & 15;
    int row0 = (t >> 2) * 64, col0 = (t & 3) * 64;
    const float* A = g_pts + (size_t)chunk * BIN * D;
    float* C = g_dm + (size_t)chunk * BIN * BIN;

    __shared__ float As[64][17];
    __shared__ float Bs[64][17];

    int tid = threadIdx.x;
    int tx = tid & 15, ty = tid >> 4;

    float acc[4][4];
#pragma unroll
    for (int m = 0; m < 4; m++)
#pragma unroll
        for (int n = 0; n < 4; n++) acc[m][n] = 0.f;

    for (int kt = 0; kt < D; kt += 16) {
#pragma unroll
        for (int q = 0; q < 4; q++) {
            int e = tid + 256 * q;
            int r = e >> 4, kk = e & 15;
            As[r][kk] = A[(row0 + r) * D + kt + kk];
            Bs[r][kk] = A[(col0 + r) * D + kt + kk];
        }
        __syncthreads();
#pragma unroll
        for (int kk = 0; kk < 16; kk++) {
            float a[4], b[4];
#pragma unroll
            for (int m = 0; m < 4; m++) a[m] = As[ty * 4 + m][kk];
#pragma unroll
            for (int n = 0; n < 4; n++) b[n] = Bs[tx * 4 + n][kk];
#pragma unroll
            for (int m = 0; m < 4; m++)
#pragma unroll
                for (int n = 0; n < 4; n++) acc[m][n] += a[m] * b[n];
        }
        __syncthreads();
    }

#pragma unroll
    for (int m = 0; m < 4; m++) {
        int rr = row0 + ty * 4 + m;
#pragma unroll
        for (int n = 0; n < 4; n++) {
            int cc = col0 + tx * 4 + n;
            float z = acc[m][n];
            C[rr * BIN + cc] = 1.f / (1.f + expf(-z)); // accurate expf: saturation matches XLA
        }
    }
}

// ---------------- K5: top-16 per row (index tie-break) + scatter -------------
// one warp per row; 16384 rows total
__global__ __launch_bounds__(256) void k_topk_scatter(float* __restrict__ out) {
    int warp = threadIdx.x >> 5, lane = threadIdx.x & 31;
    int row_g = blockIdx.x * 8 + warp; // in [0, NCHUNK*BIN) == [0, B*NPTS)
    const float* r = g_dm + (size_t)row_g * BIN;

    float v[8];
#pragma unroll
    for (int q = 0; q < 8; q++) v[q] = r[lane + 32 * q];

    int b = row_g >> 13;          // / NPTS
    int jrow = row_g & (NPTS - 1);
    int chunkbase = jrow & ~(BIN - 1);
    int gsrc = g_order[b * NPTS + jrow];
    float* outb = out + (size_t)b * NPTS * NPTS + (size_t)gsrc * NPTS;

    for (int it = 0; it < TOPK; it++) {
        float bv = -1e30f; int bc = BIN;
#pragma unroll
        for (int q = 0; q < 8; q++) {
            int c = lane + 32 * q;
            float val = v[q];
            if (val > bv || (val == bv && c < bc)) { bv = val; bc = c; }
        }
#pragma unroll
        for (int off = 16; off; off >>= 1) {
            float ov = __shfl_xor_sync(0xFFFFFFFFu, bv, off);
            int   oc = __shfl_xor_sync(0xFFFFFFFFu, bc, off);
            if (ov > bv || (ov == bv && oc < bc)) { bv = ov; bc = oc; }
        }
        // butterfly: all lanes agree on (bv, bc)
        if ((bc & 31) == lane) v[bc >> 5] = -1e30f; // mark consumed
        if (lane == 0) {
            int gdst = g_order[b * NPTS + chunkbase + bc];
            outb[gdst] = bv; // (gsrc, gdst) provably unique -> plain store
        }
    }
}

// ---------------- launch ------------------------------------------------------
extern "C" void kernel_launch(void* const* d_in, const int* in_sizes, int n_in,
                              void* d_out, int out_size) {
    const float* x  = (const float*)d_in[0]; // (2, 8192, 256) f32
    const float* cb = (const float*)d_in[1]; // (256, 32) f32
    float* out = (float*)d_out;              // (2, 8192, 8192) f32

    const long n4 = (long)B * NPTS * NPTS / 4; // 33,554,432 float4
    k_zero<<<8192, 256>>>((float4*)out, n4);

    k_proj_argmax<<<(B * NPTS) / 64, 256>>>(x, cb);
    k_stable_sort<<<B, 1024>>>();
    k_gather<<<(B * NPTS * (D / 4) + 255) / 256, 256>>>(x);
    k_gemm_sigmoid<<<NCHUNK * 16, 256>>>();
    k_topk_scatter<<<(B * NPTS) / 8, 256>>>(out);
}

// round 2
// speedup vs baseline: 1.3197x; 1.3197x over previous
#include <cuda_runtime.h>
#include <cstdint>

// Problem constants (fixed by setup_inputs)
#define B      2
#define NPTS   8192
#define D      256
#define NBINS  32
#define BIN    256
#define TOPK   16
#define NPROJ  16          // n_bins / 2
#define NCHUNK (B * NBINS) // 64 total chunks across batches

// ---------------- scratch (device globals; no allocation allowed) ------------
__device__ int   g_bin_idx[B * NPTS];
__device__ int   g_order  [B * NPTS];
__device__ float g_dm     [NCHUNK * BIN * BIN]; // 16 MB sigmoid(similarity)

// ---------------- K1: projection + argmax over [proj, -proj] ------------------
__global__ __launch_bounds__(256) void k_proj_argmax(
    const float* __restrict__ x, const float* __restrict__ cb) {
    __shared__ float cbs[NPROJ][D]; // transposed codebook, first 16 columns
    int tid = threadIdx.x;
    for (int e = tid; e < D * 32; e += 256) {
        int d = e >> 5, j = e & 31;
        float v = cb[e];
        if (j < NPROJ) cbs[j][d] = v;
    }
    __syncthreads();

    int warp = tid >> 5, lane = tid & 31;
    for (int i = 0; i < 8; i++) {
        int p = blockIdx.x * 64 + warp * 8 + i;
        const float* xr = x + (size_t)p * D;
        float acc[NPROJ];
#pragma unroll
        for (int j = 0; j < NPROJ; j++) acc[j] = 0.f;
#pragma unroll
        for (int k = 0; k < 8; k++) {
            int d = lane + 32 * k;
            float xv = xr[d];
#pragma unroll
            for (int j = 0; j < NPROJ; j++) acc[j] += xv * cbs[j][d];
        }
#pragma unroll
        for (int j = 0; j < NPROJ; j++)
#pragma unroll
            for (int off = 16; off; off >>= 1)
                acc[j] += __shfl_xor_sync(0xFFFFFFFFu, acc[j], off);
        if (lane == 0) {
            float best = acc[0]; int bi = 0;
            for (int jj = 1; jj < 2 * NPROJ; jj++) {
                float v = (jj < NPROJ) ? acc[jj] : -acc[jj - NPROJ];
                if (v > best) { best = v; bi = jj; }
            }
            g_bin_idx[p] = bi;
        }
    }
}

// ---------------- K2: stable counting sort (argsort by bin id) ---------------
__global__ __launch_bounds__(1024) void k_stable_sort() {
    int batch = blockIdx.x;
    const int* bi = g_bin_idx + batch * NPTS;
    int* ord = g_order + batch * NPTS;
    __shared__ int off[NBINS + 1];
    int w = threadIdx.x >> 5, lane = threadIdx.x & 31;

    int total = 0;
    for (int it = 0; it < NPTS / 32; it++) {
        int i = it * 32 + lane;
        unsigned m = __ballot_sync(0xFFFFFFFFu, bi[i] == w);
        total += __popc(m);
    }
    if (lane == 0) off[w + 1] = total;
    __syncthreads();
    if (threadIdx.x == 0) {
        off[0] = 0;
        for (int j = 1; j <= NBINS; j++) off[j] += off[j - 1];
    }
    __syncthreads();

    int pos = off[w];
    for (int it = 0; it < NPTS / 32; it++) {
        int i = it * 32 + lane;
        int b = bi[i];
        unsigned m = __ballot_sync(0xFFFFFFFFu, b == w);
        if (b == w) ord[pos + __popc(m & ((1u << lane) - 1u))] = i;
        pos += __popc(m);
    }
}

// ---------------- K3: fused gather + GEMM (C = P P^T) + sigmoid --------------
// grid: NCHUNK*4 blocks; each block computes a 128x128 tile, 256 threads, 8x8 acc
__global__ __launch_bounds__(256, 2) void k_gemm_sigmoid(const float* __restrict__ x) {
    __shared__ float As[8][132];
    __shared__ float Bs[8][132];

    int chunk = blockIdx.x >> 2;
    int b     = chunk >> 5;           // NBINS = 32
    int cbase = (chunk & 31) * BIN;   // chunk row base within batch
    int row0  = ((blockIdx.x >> 1) & 1) * 128;
    int col0  = (blockIdx.x & 1) * 128;

    int tid = threadIdx.x;
    int halfrow = tid >> 1;   // 0..127
    int q = tid & 1;          // which float4 within 8-wide k window

    // gather fused: indirect row pointers via g_order (rows are 1KB contiguous)
    int srcA = g_order[b * NPTS + cbase + row0 + halfrow];
    int srcB = g_order[b * NPTS + cbase + col0 + halfrow];
    const float4* pA = (const float4*)(x + ((size_t)b * NPTS + srcA) * D) + q;
    const float4* pB = (const float4*)(x + ((size_t)b * NPTS + srcB) * D) + q;

    int tx = tid & 15, ty = tid >> 4;

    float acc[8][8];
#pragma unroll
    for (int i = 0; i < 8; i++)
#pragma unroll
        for (int j = 0; j < 8; j++) acc[i][j] = 0.f;

    for (int kt = 0; kt < D; kt += 8) {
        float4 va = pA[kt >> 2];
        float4 vb = pB[kt >> 2];
        __syncthreads(); // previous iteration's reads complete before overwrite
        As[4 * q + 0][halfrow] = va.x;
        As[4 * q + 1][halfrow] = va.y;
        As[4 * q + 2][halfrow] = va.z;
        As[4 * q + 3][halfrow] = va.w;
        Bs[4 * q + 0][halfrow] = vb.x;
        Bs[4 * q + 1][halfrow] = vb.y;
        Bs[4 * q + 2][halfrow] = vb.z;
        Bs[4 * q + 3][halfrow] = vb.w;
        __syncthreads();
#pragma unroll
        for (int kk = 0; kk < 8; kk++) {
            float a[8], bb[8];
#pragma unroll
            for (int i = 0; i < 8; i++) a[i] = As[kk][ty * 8 + i];
#pragma unroll
            for (int j = 0; j < 8; j++) bb[j] = Bs[kk][tx * 8 + j];
#pragma unroll
            for (int i = 0; i < 8; i++)
#pragma unroll
                for (int j = 0; j < 8; j++) acc[i][j] += a[i] * bb[j];
        }
    }

    float* C = g_dm + (size_t)chunk * BIN * BIN;
#pragma unroll
    for (int i = 0; i < 8; i++) {
        int rr = row0 + ty * 8 + i;
#pragma unroll
        for (int jj = 0; jj < 2; jj++) {
            float4 o;
            o.x = 1.f / (1.f + expf(-acc[i][4 * jj + 0]));
            o.y = 1.f / (1.f + expf(-acc[i][4 * jj + 1]));
            o.z = 1.f / (1.f + expf(-acc[i][4 * jj + 2]));
            o.w = 1.f / (1.f + expf(-acc[i][4 * jj + 3]));
            *(float4*)(C + (size_t)rr * BIN + col0 + tx * 8 + 4 * jj) = o;
        }
    }
}

// ---------------- K4: fused zero + top-16 + scatter ---------------------------
// one block per output row; warp 0: top-k via REDUX; warps 1-7: zero the row
__global__ __launch_bounds__(256) void k_write(float* __restrict__ out) {
    int row_g = blockIdx.x;              // [0, B*NPTS)
    int lane = threadIdx.x & 31, w = threadIdx.x >> 5;
    int b = row_g >> 13;                 // / NPTS
    int jrow = row_g & (NPTS - 1);
    int gsrc = g_order[row_g];
    float* orow = out + ((size_t)b * NPTS + gsrc) * NPTS;

    __shared__ int   sidx[TOPK];
    __shared__ float sval[TOPK];

    if (w == 0) {
        const float* r = g_dm + (size_t)row_g * BIN;
        unsigned u[8];
#pragma unroll
        for (int q = 0; q < 8; q++) u[q] = __float_as_uint(r[lane + 32 * q]);
        int chunkoff = b * NPTS + (jrow & ~(BIN - 1));
        for (int it = 0; it < TOPK; it++) {
            unsigned best = 0u; int bc = BIN;
#pragma unroll
            for (int q = 0; q < 8; q++) {
                // ascending c within lane + strict '>' keeps the min col on ties
                if (u[q] > best) { best = u[q]; bc = lane + 32 * q; }
            }
            unsigned m = __reduce_max_sync(0xFFFFFFFFu, best);
            int cand = (best == m) ? bc : (1 << 30);
            int cmin = __reduce_min_sync(0xFFFFFFFFu, cand);
            if ((cmin & 31) == lane) u[cmin >> 5] = 0u; // sigmoid > 0: 0 == consumed
            if (lane == 0) {
                sval[it] = __uint_as_float(m);
                sidx[it] = g_order[chunkoff + cmin];
            }
        }
    } else {
        float4 z = make_float4(0.f, 0.f, 0.f, 0.f);
        float4* o4 = (float4*)orow;
        for (int i = threadIdx.x - 32; i < NPTS / 4; i += 224) o4[i] = z;
    }
    __syncthreads();
    if (threadIdx.x < TOPK) orow[sidx[threadIdx.x]] = sval[threadIdx.x];
}

// ---------------- launch ------------------------------------------------------
extern "C" void kernel_launch(void* const* d_in, const int* in_sizes, int n_in,
                              void* d_out, int out_size) {
    const float* x  = (const float*)d_in[0]; // (2, 8192, 256) f32
    const float* cb = (const float*)d_in[1]; // (256, 32) f32
    float* out = (float*)d_out;              // (2, 8192, 8192) f32

    k_proj_argmax<<<(B * NPTS) / 64, 256>>>(x, cb);
    k_stable_sort<<<B, 1024>>>();
    k_gemm_sigmoid<<<NCHUNK * 4, 256>>>(x);
    k_write<<<B * NPTS, 256>>>(out);
}